// round 15
// baseline (speedup 1.0000x reference)
#include <cuda_runtime.h>
#include <cuda_bf16.h>
#include <float.h>
#include <math.h>

#define B_SEG 16
#define INC 128
#define HID 32
#define CHUNK 256          // rows per reduce block

// Scratch (no allocations allowed). Zero-initialized at module load; the gate
// kernel restores zeros after consuming, so every graph replay sees zeros.
__device__ float    g_sum [B_SEG * INC];
__device__ unsigned g_maxk[B_SEG * INC];
__device__ float    g_gate[B_SEG * INC];
__device__ int      g_off [B_SEG + 1];

// Monotone float <-> unsigned key for atomicMax (key 0 < key(any float))
__device__ __forceinline__ unsigned orderFloat(float f) {
    unsigned u = __float_as_uint(f);
    return (u & 0x80000000u) ? ~u : (u | 0x80000000u);
}
__device__ __forceinline__ float unorderFloat(unsigned k) {
    return (k & 0x80000000u) ? __uint_as_float(k & 0x7fffffffu)
                             : __uint_as_float(~k);
}

// Reduce: one 256-row chunk per block. O(1) boundary detection from sorted
// bidx; block-level smem reduction before global atomics.
__global__ void __launch_bounds__(256, 8)
reduce_kernel(const float4* __restrict__ f,
              const int*    __restrict__ bidx,
              int n_rows) {
    int t      = threadIdx.x;
    int rowoff = t >> 5;            // warp id (0..7)
    int c4     = t & 31;            // float4 lane within row

    int r0 = blockIdx.x * CHUNK;
    int r1 = min(r0 + CHUNK, n_rows);

    __shared__ int    off_s[B_SEG + 1];
    __shared__ float4 sum_s[8 * 32];   // 4 KB
    __shared__ float4 max_s4[8 * 32];  // 4 KB

    // ---- O(1) boundary marking (bidx sorted) ----
    int r = r0 + t;
    if (r < r1) {
        int v  = __ldg(&bidx[r]);
        int vp = (r == 0) ? -1 : __ldg(&bidx[r - 1]);
        if (r == r0) {
            for (int b = 0; b <= vp; b++) off_s[b] = r0;
        }
        for (int b = vp + 1; b <= v; b++) {
            off_s[b] = r;          // chunk-local lower bound
            g_off[b] = r;          // true global lower bound
        }
        if (r == r1 - 1) {
            for (int b = v + 1; b <= B_SEG; b++) off_s[b] = r1;
            if (r == n_rows - 1)
                for (int b = v + 1; b <= B_SEG; b++) g_off[b] = n_rows;
        }
    }
    __syncthreads();

    if (r0 >= n_rows) return;

    for (int b = 0; b < B_SEG; b++) {
        int a = off_s[b];
        int e = off_s[b + 1];
        if (a >= e) continue;

        float4 sum = make_float4(0.f, 0.f, 0.f, 0.f);
        float4 mx  = make_float4(-FLT_MAX, -FLT_MAX, -FLT_MAX, -FLT_MAX);

        int rr = a + rowoff;
        // 4 unguarded 128b loads per iter (front-batched)
        for (; rr + 24 < e; rr += 32) {
            const float4* p = &f[(size_t)rr * 32 + c4];
            float4 v0 = __ldg(p);
            float4 v1 = __ldg(p +  8 * 32);
            float4 v2 = __ldg(p + 16 * 32);
            float4 v3 = __ldg(p + 24 * 32);
            sum.x += (v0.x + v1.x) + (v2.x + v3.x);
            sum.y += (v0.y + v1.y) + (v2.y + v3.y);
            sum.z += (v0.z + v1.z) + (v2.z + v3.z);
            sum.w += (v0.w + v1.w) + (v2.w + v3.w);
            mx.x = fmaxf(mx.x, fmaxf(fmaxf(v0.x, v1.x), fmaxf(v2.x, v3.x)));
            mx.y = fmaxf(mx.y, fmaxf(fmaxf(v0.y, v1.y), fmaxf(v2.y, v3.y)));
            mx.z = fmaxf(mx.z, fmaxf(fmaxf(v0.z, v1.z), fmaxf(v2.z, v3.z)));
            mx.w = fmaxf(mx.w, fmaxf(fmaxf(v0.w, v1.w), fmaxf(v2.w, v3.w)));
        }
        for (; rr < e; rr += 8) {
            float4 v = __ldg(&f[(size_t)rr * 32 + c4]);
            sum.x += v.x; sum.y += v.y; sum.z += v.z; sum.w += v.w;
            mx.x = fmaxf(mx.x, v.x); mx.y = fmaxf(mx.y, v.y);
            mx.z = fmaxf(mx.z, v.z); mx.w = fmaxf(mx.w, v.w);
        }

        // block reduce (barriers reached uniformly by all 256 threads)
        __syncthreads();
        sum_s [rowoff * 32 + c4] = sum;
        max_s4[rowoff * 32 + c4] = mx;
        __syncthreads();
        if (t < INC) {
            const float* ss = (const float*)sum_s;   // [warp][128 floats]
            const float* ms = (const float*)max_s4;
            float s = ss[t], m = ms[t];
            #pragma unroll
            for (int w = 1; w < 8; w++) {
                s += ss[w * INC + t];
                m  = fmaxf(m, ms[w * INC + t]);
            }
            atomicAdd(&g_sum[b * INC + t], s);
            atomicMax(&g_maxk[b * INC + t], orderFloat(m));
        }
        __syncthreads();
    }
}

// Gate: 16 blocks, one segment each, 128 threads. Restores accumulator zeros
// for the next graph replay.
__global__ void __launch_bounds__(128)
gate_kernel(const float* __restrict__ W1,
            const float* __restrict__ b1,
            const float* __restrict__ W2,
            const float* __restrict__ b2) {
    int b = blockIdx.x;         // segment
    int t = threadIdx.x;

    __shared__ float mean_sh[INC];
    __shared__ float max_sh [INC];
    __shared__ float hid_s[2 * HID];    // [mean-hid 32 | max-hid 32]

    int o0 = g_off[b], o1 = g_off[b + 1];
    int cnt = o1 - o0;
    float inv = 1.0f / fmaxf((float)cnt, 1.0f);

    mean_sh[t] = g_sum[b * INC + t] * inv;
    max_sh[t]  = (cnt > 0) ? unorderFloat(g_maxk[b * INC + t]) : 0.0f;
    // restore zeros for next graph replay
    g_sum[b * INC + t]  = 0.0f;
    g_maxk[b * INC + t] = 0u;
    __syncthreads();

    // Layer 1: 64 dot products (32 hid x {mean,max}); threads 0-63.
    if (t < 2 * HID) {
        int h   = t & 31;
        int sel = t >> 5;                   // 0: mean, 1: max
        const float* src = sel ? max_sh : mean_sh;
        float acc = __ldg(&b1[h]);
        #pragma unroll 8
        for (int c = 0; c < INC; c++)
            acc = fmaf(src[c], __ldg(&W1[c * HID + h]), acc);
        hid_s[sel * HID + h] = fmaxf(acc, 0.0f);
    }
    __syncthreads();

    // Layer 2: 128 outputs; one per thread.
    float om = __ldg(&b2[t]), ox = om;
    #pragma unroll 8
    for (int hh = 0; hh < HID; hh++) {
        float w = __ldg(&W2[hh * INC + t]);
        om = fmaf(hid_s[hh], w, om);
        ox = fmaf(hid_s[HID + hh], w, ox);
    }
    float z = om + ox;
    g_gate[b * INC + t] = 1.0f / (1.0f + __expf(-z));
}

// Streaming scale: out = feats * gate[batch_idx]. Contiguous 1024-float4
// chunk per block, blocks mapped in REVERSE so the first-scheduled blocks
// read the array tail the reduce left L2-resident. Streaming cache hints
// (__ldcs/__stcs) keep scale's own traffic from evicting that window.
__global__ void __launch_bounds__(256)
scale_kernel(const float4* __restrict__ f,
             const int*    __restrict__ bidx,
             float4* __restrict__ out,
             size_t nvec) {
    int t = threadIdx.x;
    size_t blk  = (size_t)(gridDim.x - 1 - blockIdx.x);   // reversed mapping
    size_t base = blk * 1024;
    const float4* gate4 = (const float4*)g_gate;

    size_t i0 = base + t;
    size_t i1 = base + t + 256;
    size_t i2 = base + t + 512;
    size_t i3 = base + t + 768;

    float4 v0, v1, v2, v3;
    int s0 = 0, s1 = 0, s2 = 0, s3 = 0;
    if (i0 < nvec) { v0 = __ldcs(&f[i0]); s0 = __ldg(&bidx[i0 >> 5]); }
    if (i1 < nvec) { v1 = __ldcs(&f[i1]); s1 = __ldg(&bidx[i1 >> 5]); }
    if (i2 < nvec) { v2 = __ldcs(&f[i2]); s2 = __ldg(&bidx[i2 >> 5]); }
    if (i3 < nvec) { v3 = __ldcs(&f[i3]); s3 = __ldg(&bidx[i3 >> 5]); }

    if (i0 < nvec) {
        float4 g = gate4[s0 * 32 + (i0 & 31)];
        v0.x *= g.x; v0.y *= g.y; v0.z *= g.z; v0.w *= g.w;
        __stcs(&out[i0], v0);
    }
    if (i1 < nvec) {
        float4 g = gate4[s1 * 32 + (i1 & 31)];
        v1.x *= g.x; v1.y *= g.y; v1.z *= g.z; v1.w *= g.w;
        __stcs(&out[i1], v1);
    }
    if (i2 < nvec) {
        float4 g = gate4[s2 * 32 + (i2 & 31)];
        v2.x *= g.x; v2.y *= g.y; v2.z *= g.z; v2.w *= g.w;
        __stcs(&out[i2], v2);
    }
    if (i3 < nvec) {
        float4 g = gate4[s3 * 32 + (i3 & 31)];
        v3.x *= g.x; v3.y *= g.y; v3.z *= g.z; v3.w *= g.w;
        __stcs(&out[i3], v3);
    }
}

extern "C" void kernel_launch(void* const* d_in, const int* in_sizes, int n_in,
                              void* d_out, int out_size) {
    const float* feats = (const float*)d_in[0];
    const int*   bidx  = (const int*)d_in[1];
    const float* W1    = (const float*)d_in[2];
    const float* b1    = (const float*)d_in[3];
    const float* W2    = (const float*)d_in[4];
    const float* b2    = (const float*)d_in[5];
    float* out = (float*)d_out;

    int n_rows = in_sizes[1];                   // N points
    size_t nvec = (size_t)n_rows * (INC / 4);   // float4 count

    // Fine-grained multi-wave grid: one 256-row chunk per block.
    int red_blocks = (n_rows + CHUNK - 1) / CHUNK;
    reduce_kernel<<<red_blocks, 256>>>((const float4*)feats, bidx, n_rows);

    gate_kernel<<<B_SEG, 128>>>(W1, b1, W2, b2);

    int sblocks = (int)((nvec + 1023) / 1024);
    scale_kernel<<<sblocks, 256>>>((const float4*)feats, bidx,
                                   (float4*)out, nvec);
}

// round 16
// speedup vs baseline: 1.0115x; 1.0115x over previous
#include <cuda_runtime.h>
#include <cuda_bf16.h>
#include <float.h>
#include <math.h>

#define B_SEG 16
#define INC 128
#define HID 32
#define CHUNK 256          // rows per reduce block

// Scratch (no allocations allowed). Zero-initialized at module load; the gate
// kernel restores zeros after consuming, so every graph replay sees zeros.
__device__ float    g_sum [B_SEG * INC];
__device__ unsigned g_maxk[B_SEG * INC];
__device__ float    g_gate[B_SEG * INC];
__device__ int      g_off [B_SEG + 1];

// Monotone float <-> unsigned key for atomicMax (key 0 < key(any float))
__device__ __forceinline__ unsigned orderFloat(float f) {
    unsigned u = __float_as_uint(f);
    return (u & 0x80000000u) ? ~u : (u | 0x80000000u);
}
__device__ __forceinline__ float unorderFloat(unsigned k) {
    return (k & 0x80000000u) ? __uint_as_float(k & 0x7fffffffu)
                             : __uint_as_float(~k);
}

// Reduce: one 256-row chunk per block. O(1) boundary detection from sorted
// bidx; block-level smem reduction before global atomics.
__global__ void __launch_bounds__(256, 8)
reduce_kernel(const float4* __restrict__ f,
              const int*    __restrict__ bidx,
              int n_rows) {
    int t      = threadIdx.x;
    int rowoff = t >> 5;            // warp id (0..7)
    int c4     = t & 31;            // float4 lane within row

    int r0 = blockIdx.x * CHUNK;
    int r1 = min(r0 + CHUNK, n_rows);

    __shared__ int    off_s[B_SEG + 1];
    __shared__ float4 sum_s[8 * 32];   // 4 KB
    __shared__ float4 max_s4[8 * 32];  // 4 KB

    // ---- O(1) boundary marking (bidx sorted) ----
    int r = r0 + t;
    if (r < r1) {
        int v  = __ldg(&bidx[r]);
        int vp = (r == 0) ? -1 : __ldg(&bidx[r - 1]);
        if (r == r0) {
            for (int b = 0; b <= vp; b++) off_s[b] = r0;
        }
        for (int b = vp + 1; b <= v; b++) {
            off_s[b] = r;          // chunk-local lower bound
            g_off[b] = r;          // true global lower bound
        }
        if (r == r1 - 1) {
            for (int b = v + 1; b <= B_SEG; b++) off_s[b] = r1;
            if (r == n_rows - 1)
                for (int b = v + 1; b <= B_SEG; b++) g_off[b] = n_rows;
        }
    }
    __syncthreads();

    if (r0 >= n_rows) return;

    for (int b = 0; b < B_SEG; b++) {
        int a = off_s[b];
        int e = off_s[b + 1];
        if (a >= e) continue;

        float4 sum = make_float4(0.f, 0.f, 0.f, 0.f);
        float4 mx  = make_float4(-FLT_MAX, -FLT_MAX, -FLT_MAX, -FLT_MAX);

        int rr = a + rowoff;
        // 4 unguarded 128b loads per iter (front-batched)
        for (; rr + 24 < e; rr += 32) {
            const float4* p = &f[(size_t)rr * 32 + c4];
            float4 v0 = __ldg(p);
            float4 v1 = __ldg(p +  8 * 32);
            float4 v2 = __ldg(p + 16 * 32);
            float4 v3 = __ldg(p + 24 * 32);
            sum.x += (v0.x + v1.x) + (v2.x + v3.x);
            sum.y += (v0.y + v1.y) + (v2.y + v3.y);
            sum.z += (v0.z + v1.z) + (v2.z + v3.z);
            sum.w += (v0.w + v1.w) + (v2.w + v3.w);
            mx.x = fmaxf(mx.x, fmaxf(fmaxf(v0.x, v1.x), fmaxf(v2.x, v3.x)));
            mx.y = fmaxf(mx.y, fmaxf(fmaxf(v0.y, v1.y), fmaxf(v2.y, v3.y)));
            mx.z = fmaxf(mx.z, fmaxf(fmaxf(v0.z, v1.z), fmaxf(v2.z, v3.z)));
            mx.w = fmaxf(mx.w, fmaxf(fmaxf(v0.w, v1.w), fmaxf(v2.w, v3.w)));
        }
        for (; rr < e; rr += 8) {
            float4 v = __ldg(&f[(size_t)rr * 32 + c4]);
            sum.x += v.x; sum.y += v.y; sum.z += v.z; sum.w += v.w;
            mx.x = fmaxf(mx.x, v.x); mx.y = fmaxf(mx.y, v.y);
            mx.z = fmaxf(mx.z, v.z); mx.w = fmaxf(mx.w, v.w);
        }

        // block reduce (barriers reached uniformly by all 256 threads)
        __syncthreads();
        sum_s [rowoff * 32 + c4] = sum;
        max_s4[rowoff * 32 + c4] = mx;
        __syncthreads();
        if (t < INC) {
            const float* ss = (const float*)sum_s;   // [warp][128 floats]
            const float* ms = (const float*)max_s4;
            float s = ss[t], m = ms[t];
            #pragma unroll
            for (int w = 1; w < 8; w++) {
                s += ss[w * INC + t];
                m  = fmaxf(m, ms[w * INC + t]);
            }
            atomicAdd(&g_sum[b * INC + t], s);
            atomicMax(&g_maxk[b * INC + t], orderFloat(m));
        }
        __syncthreads();
    }
}

// Gate: 16 blocks, one segment each, 128 threads. Restores accumulator zeros
// for the next graph replay.
__global__ void __launch_bounds__(128)
gate_kernel(const float* __restrict__ W1,
            const float* __restrict__ b1,
            const float* __restrict__ W2,
            const float* __restrict__ b2) {
    int b = blockIdx.x;         // segment
    int t = threadIdx.x;

    __shared__ float mean_sh[INC];
    __shared__ float max_sh [INC];
    __shared__ float hid_s[2 * HID];    // [mean-hid 32 | max-hid 32]

    int o0 = g_off[b], o1 = g_off[b + 1];
    int cnt = o1 - o0;
    float inv = 1.0f / fmaxf((float)cnt, 1.0f);

    mean_sh[t] = g_sum[b * INC + t] * inv;
    max_sh[t]  = (cnt > 0) ? unorderFloat(g_maxk[b * INC + t]) : 0.0f;
    // restore zeros for next graph replay
    g_sum[b * INC + t]  = 0.0f;
    g_maxk[b * INC + t] = 0u;
    __syncthreads();

    // Layer 1: 64 dot products (32 hid x {mean,max}); threads 0-63.
    if (t < 2 * HID) {
        int h   = t & 31;
        int sel = t >> 5;                   // 0: mean, 1: max
        const float* src = sel ? max_sh : mean_sh;
        float acc = __ldg(&b1[h]);
        #pragma unroll 8
        for (int c = 0; c < INC; c++)
            acc = fmaf(src[c], __ldg(&W1[c * HID + h]), acc);
        hid_s[sel * HID + h] = fmaxf(acc, 0.0f);
    }
    __syncthreads();

    // Layer 2: 128 outputs; one per thread.
    float om = __ldg(&b2[t]), ox = om;
    #pragma unroll 8
    for (int hh = 0; hh < HID; hh++) {
        float w = __ldg(&W2[hh * INC + t]);
        om = fmaf(hid_s[hh], w, om);
        ox = fmaf(hid_s[HID + hh], w, ox);
    }
    float z = om + ox;
    g_gate[b * INC + t] = 1.0f / (1.0f + __expf(-z));
}

// Streaming scale: out = feats * gate[batch_idx]. Contiguous 1024-float4
// chunk per block, blocks mapped in REVERSE so the first-scheduled blocks
// read the array tail the reduce left L2-resident. Output stores use __stcs
// (evict-first) so the never-re-read output doesn't evict the feats window;
// feats loads stay default-policy (upcoming blocks need those lines in L2).
__global__ void __launch_bounds__(256)
scale_kernel(const float4* __restrict__ f,
             const int*    __restrict__ bidx,
             float4* __restrict__ out,
             size_t nvec) {
    int t = threadIdx.x;
    size_t blk  = (size_t)(gridDim.x - 1 - blockIdx.x);   // reversed mapping
    size_t base = blk * 1024;
    const float4* gate4 = (const float4*)g_gate;

    size_t i0 = base + t;
    size_t i1 = base + t + 256;
    size_t i2 = base + t + 512;
    size_t i3 = base + t + 768;

    float4 v0, v1, v2, v3;
    int s0 = 0, s1 = 0, s2 = 0, s3 = 0;
    if (i0 < nvec) { v0 = __ldg(&f[i0]); s0 = __ldg(&bidx[i0 >> 5]); }
    if (i1 < nvec) { v1 = __ldg(&f[i1]); s1 = __ldg(&bidx[i1 >> 5]); }
    if (i2 < nvec) { v2 = __ldg(&f[i2]); s2 = __ldg(&bidx[i2 >> 5]); }
    if (i3 < nvec) { v3 = __ldg(&f[i3]); s3 = __ldg(&bidx[i3 >> 5]); }

    if (i0 < nvec) {
        float4 g = gate4[s0 * 32 + (i0 & 31)];
        v0.x *= g.x; v0.y *= g.y; v0.z *= g.z; v0.w *= g.w;
        __stcs(&out[i0], v0);
    }
    if (i1 < nvec) {
        float4 g = gate4[s1 * 32 + (i1 & 31)];
        v1.x *= g.x; v1.y *= g.y; v1.z *= g.z; v1.w *= g.w;
        __stcs(&out[i1], v1);
    }
    if (i2 < nvec) {
        float4 g = gate4[s2 * 32 + (i2 & 31)];
        v2.x *= g.x; v2.y *= g.y; v2.z *= g.z; v2.w *= g.w;
        __stcs(&out[i2], v2);
    }
    if (i3 < nvec) {
        float4 g = gate4[s3 * 32 + (i3 & 31)];
        v3.x *= g.x; v3.y *= g.y; v3.z *= g.z; v3.w *= g.w;
        __stcs(&out[i3], v3);
    }
}

extern "C" void kernel_launch(void* const* d_in, const int* in_sizes, int n_in,
                              void* d_out, int out_size) {
    const float* feats = (const float*)d_in[0];
    const int*   bidx  = (const int*)d_in[1];
    const float* W1    = (const float*)d_in[2];
    const float* b1    = (const float*)d_in[3];
    const float* W2    = (const float*)d_in[4];
    const float* b2    = (const float*)d_in[5];
    float* out = (float*)d_out;

    int n_rows = in_sizes[1];                   // N points
    size_t nvec = (size_t)n_rows * (INC / 4);   // float4 count

    // Fine-grained multi-wave grid: one 256-row chunk per block.
    int red_blocks = (n_rows + CHUNK - 1) / CHUNK;
    reduce_kernel<<<red_blocks, 256>>>((const float4*)feats, bidx, n_rows);

    gate_kernel<<<B_SEG, 128>>>(W1, b1, W2, b2);

    int sblocks = (int)((nvec + 1023) / 1024);
    scale_kernel<<<sblocks, 256>>>((const float4*)feats, bidx,
                                   (float4*)out, nvec);
}

// round 17
// speedup vs baseline: 1.0187x; 1.0071x over previous
#include <cuda_runtime.h>
#include <cuda_bf16.h>
#include <float.h>
#include <math.h>

#define B_SEG 16
#define INC 128
#define HID 32
#define CHUNK 256          // rows per reduce block

// Scratch (no allocations allowed). Zero-initialized at module load; the gate
// kernel restores zeros after consuming, so every graph replay sees zeros.
__device__ float    g_sum [B_SEG * INC];
__device__ unsigned g_maxk[B_SEG * INC];
__device__ float    g_gate[B_SEG * INC];
__device__ int      g_off [B_SEG + 1];

// Monotone float <-> unsigned key for atomicMax (key 0 < key(any float))
__device__ __forceinline__ unsigned orderFloat(float f) {
    unsigned u = __float_as_uint(f);
    return (u & 0x80000000u) ? ~u : (u | 0x80000000u);
}
__device__ __forceinline__ float unorderFloat(unsigned k) {
    return (k & 0x80000000u) ? __uint_as_float(k & 0x7fffffffu)
                             : __uint_as_float(~k);
}

// Reduce: one 256-row chunk per block. O(1) boundary detection from sorted
// bidx; block-level smem reduction before global atomics.
__global__ void __launch_bounds__(256, 8)
reduce_kernel(const float4* __restrict__ f,
              const int*    __restrict__ bidx,
              int n_rows) {
    int t      = threadIdx.x;
    int rowoff = t >> 5;            // warp id (0..7)
    int c4     = t & 31;            // float4 lane within row

    int r0 = blockIdx.x * CHUNK;
    int r1 = min(r0 + CHUNK, n_rows);

    __shared__ int    off_s[B_SEG + 1];
    __shared__ float4 sum_s[8 * 32];   // 4 KB
    __shared__ float4 max_s4[8 * 32];  // 4 KB

    // ---- O(1) boundary marking (bidx sorted) ----
    int r = r0 + t;
    if (r < r1) {
        int v  = __ldg(&bidx[r]);
        int vp = (r == 0) ? -1 : __ldg(&bidx[r - 1]);
        if (r == r0) {
            for (int b = 0; b <= vp; b++) off_s[b] = r0;
        }
        for (int b = vp + 1; b <= v; b++) {
            off_s[b] = r;          // chunk-local lower bound
            g_off[b] = r;          // true global lower bound
        }
        if (r == r1 - 1) {
            for (int b = v + 1; b <= B_SEG; b++) off_s[b] = r1;
            if (r == n_rows - 1)
                for (int b = v + 1; b <= B_SEG; b++) g_off[b] = n_rows;
        }
    }
    __syncthreads();

    if (r0 >= n_rows) return;

    for (int b = 0; b < B_SEG; b++) {
        int a = off_s[b];
        int e = off_s[b + 1];
        if (a >= e) continue;

        float4 sum = make_float4(0.f, 0.f, 0.f, 0.f);
        float4 mx  = make_float4(-FLT_MAX, -FLT_MAX, -FLT_MAX, -FLT_MAX);

        int rr = a + rowoff;
        // 4 unguarded 128b loads per iter (front-batched)
        for (; rr + 24 < e; rr += 32) {
            const float4* p = &f[(size_t)rr * 32 + c4];
            float4 v0 = __ldg(p);
            float4 v1 = __ldg(p +  8 * 32);
            float4 v2 = __ldg(p + 16 * 32);
            float4 v3 = __ldg(p + 24 * 32);
            sum.x += (v0.x + v1.x) + (v2.x + v3.x);
            sum.y += (v0.y + v1.y) + (v2.y + v3.y);
            sum.z += (v0.z + v1.z) + (v2.z + v3.z);
            sum.w += (v0.w + v1.w) + (v2.w + v3.w);
            mx.x = fmaxf(mx.x, fmaxf(fmaxf(v0.x, v1.x), fmaxf(v2.x, v3.x)));
            mx.y = fmaxf(mx.y, fmaxf(fmaxf(v0.y, v1.y), fmaxf(v2.y, v3.y)));
            mx.z = fmaxf(mx.z, fmaxf(fmaxf(v0.z, v1.z), fmaxf(v2.z, v3.z)));
            mx.w = fmaxf(mx.w, fmaxf(fmaxf(v0.w, v1.w), fmaxf(v2.w, v3.w)));
        }
        for (; rr < e; rr += 8) {
            float4 v = __ldg(&f[(size_t)rr * 32 + c4]);
            sum.x += v.x; sum.y += v.y; sum.z += v.z; sum.w += v.w;
            mx.x = fmaxf(mx.x, v.x); mx.y = fmaxf(mx.y, v.y);
            mx.z = fmaxf(mx.z, v.z); mx.w = fmaxf(mx.w, v.w);
        }

        // block reduce (barriers reached uniformly by all 256 threads)
        __syncthreads();
        sum_s [rowoff * 32 + c4] = sum;
        max_s4[rowoff * 32 + c4] = mx;
        __syncthreads();
        if (t < INC) {
            const float* ss = (const float*)sum_s;   // [warp][128 floats]
            const float* ms = (const float*)max_s4;
            float s = ss[t], m = ms[t];
            #pragma unroll
            for (int w = 1; w < 8; w++) {
                s += ss[w * INC + t];
                m  = fmaxf(m, ms[w * INC + t]);
            }
            atomicAdd(&g_sum[b * INC + t], s);
            atomicMax(&g_maxk[b * INC + t], orderFloat(m));
        }
        __syncthreads();
    }
}

// Gate: 16 blocks, one segment each, 128 threads. Launched with PDL: starts
// while the reduce drains; syncs on the grid dependency before touching
// g_sum/g_maxk/g_off. Restores accumulator zeros for the next graph replay.
__global__ void __launch_bounds__(128)
gate_kernel(const float* __restrict__ W1,
            const float* __restrict__ b1,
            const float* __restrict__ W2,
            const float* __restrict__ b2) {
    int b = blockIdx.x;         // segment
    int t = threadIdx.x;

    __shared__ float mean_sh[INC];
    __shared__ float max_sh [INC];
    __shared__ float hid_s[2 * HID];    // [mean-hid 32 | max-hid 32]

    // Prefetch weights into L2 while the reduce finishes.
    float w1pre = __ldg(&W1[b * 8 * HID + t]);       // warms 16KB of W1
    (void)w1pre;

#if __CUDA_ARCH__ >= 900
    cudaGridDependencySynchronize();
#endif

    int o0 = g_off[b], o1 = g_off[b + 1];
    int cnt = o1 - o0;
    float inv = 1.0f / fmaxf((float)cnt, 1.0f);

    mean_sh[t] = g_sum[b * INC + t] * inv;
    max_sh[t]  = (cnt > 0) ? unorderFloat(g_maxk[b * INC + t]) : 0.0f;
    // restore zeros for next graph replay
    g_sum[b * INC + t]  = 0.0f;
    g_maxk[b * INC + t] = 0u;
    __syncthreads();

    // Layer 1: 64 dot products (32 hid x {mean,max}); threads 0-63.
    if (t < 2 * HID) {
        int h   = t & 31;
        int sel = t >> 5;                   // 0: mean, 1: max
        const float* src = sel ? max_sh : mean_sh;
        float acc = __ldg(&b1[h]);
        #pragma unroll 8
        for (int c = 0; c < INC; c++)
            acc = fmaf(src[c], __ldg(&W1[c * HID + h]), acc);
        hid_s[sel * HID + h] = fmaxf(acc, 0.0f);
    }
    __syncthreads();

    // Layer 2: 128 outputs; one per thread.
    float om = __ldg(&b2[t]), ox = om;
    #pragma unroll 8
    for (int hh = 0; hh < HID; hh++) {
        float w = __ldg(&W2[hh * INC + t]);
        om = fmaf(hid_s[hh], w, om);
        ox = fmaf(hid_s[HID + hh], w, ox);
    }
    float z = om + ox;
    g_gate[b * INC + t] = 1.0f / (1.0f + __expf(-z));
}

// Streaming scale: out = feats * gate[batch_idx]. Contiguous 1024-float4
// chunk per block, blocks mapped in REVERSE so the first-scheduled blocks
// read the array tail the reduce left L2-resident. Launched with PDL: feats
// and bidx loads issue while the gate kernel runs; the grid-dependency sync
// guards only the tiny g_gate read.
__global__ void __launch_bounds__(256)
scale_kernel(const float4* __restrict__ f,
             const int*    __restrict__ bidx,
             float4* __restrict__ out,
             size_t nvec) {
    int t = threadIdx.x;
    size_t blk  = (size_t)(gridDim.x - 1 - blockIdx.x);   // reversed mapping
    size_t base = blk * 1024;
    const float4* gate4 = (const float4*)g_gate;

    size_t i0 = base + t;
    size_t i1 = base + t + 256;
    size_t i2 = base + t + 512;
    size_t i3 = base + t + 768;

    // Independent of the gate kernel: issue these before the dependency sync.
    float4 v0, v1, v2, v3;
    int s0 = 0, s1 = 0, s2 = 0, s3 = 0;
    if (i0 < nvec) { v0 = __ldg(&f[i0]); s0 = __ldg(&bidx[i0 >> 5]); }
    if (i1 < nvec) { v1 = __ldg(&f[i1]); s1 = __ldg(&bidx[i1 >> 5]); }
    if (i2 < nvec) { v2 = __ldg(&f[i2]); s2 = __ldg(&bidx[i2 >> 5]); }
    if (i3 < nvec) { v3 = __ldg(&f[i3]); s3 = __ldg(&bidx[i3 >> 5]); }

#if __CUDA_ARCH__ >= 900
    cudaGridDependencySynchronize();
#endif

    if (i0 < nvec) {
        float4 g = gate4[s0 * 32 + (i0 & 31)];
        v0.x *= g.x; v0.y *= g.y; v0.z *= g.z; v0.w *= g.w;
        out[i0] = v0;
    }
    if (i1 < nvec) {
        float4 g = gate4[s1 * 32 + (i1 & 31)];
        v1.x *= g.x; v1.y *= g.y; v1.z *= g.z; v1.w *= g.w;
        out[i1] = v1;
    }
    if (i2 < nvec) {
        float4 g = gate4[s2 * 32 + (i2 & 31)];
        v2.x *= g.x; v2.y *= g.y; v2.z *= g.z; v2.w *= g.w;
        out[i2] = v2;
    }
    if (i3 < nvec) {
        float4 g = gate4[s3 * 32 + (i3 & 31)];
        v3.x *= g.x; v3.y *= g.y; v3.z *= g.z; v3.w *= g.w;
        out[i3] = v3;
    }
}

extern "C" void kernel_launch(void* const* d_in, const int* in_sizes, int n_in,
                              void* d_out, int out_size) {
    const float* feats = (const float*)d_in[0];
    const int*   bidx  = (const int*)d_in[1];
    const float* W1    = (const float*)d_in[2];
    const float* b1    = (const float*)d_in[3];
    const float* W2    = (const float*)d_in[4];
    const float* b2    = (const float*)d_in[5];
    float* out = (float*)d_out;

    int n_rows = in_sizes[1];                   // N points
    size_t nvec = (size_t)n_rows * (INC / 4);   // float4 count

    int red_blocks = (n_rows + CHUNK - 1) / CHUNK;
    reduce_kernel<<<red_blocks, 256>>>((const float4*)feats, bidx, n_rows);

    // PDL launches: dependent kernels begin while predecessor drains; the
    // in-kernel cudaGridDependencySynchronize() guards dependent data.
    cudaLaunchAttribute pdl[1];
    pdl[0].id = cudaLaunchAttributeProgrammaticStreamSerialization;
    pdl[0].val.programmaticStreamSerializationAllowed = 1;

    {
        cudaLaunchConfig_t cfg = {};
        cfg.gridDim  = dim3(B_SEG, 1, 1);
        cfg.blockDim = dim3(128, 1, 1);
        cfg.attrs    = pdl;
        cfg.numAttrs = 1;
        cudaLaunchKernelEx(&cfg, gate_kernel, W1, b1, W2, b2);
    }

    {
        int sblocks = (int)((nvec + 1023) / 1024);
        cudaLaunchConfig_t cfg = {};
        cfg.gridDim  = dim3(sblocks, 1, 1);
        cfg.blockDim = dim3(256, 1, 1);
        cfg.attrs    = pdl;
        cfg.numAttrs = 1;
        cudaLaunchKernelEx(&cfg, scale_kernel,
                           (const float4*)feats, bidx, (float4*)out, nvec);
    }
}